// round 1
// baseline (speedup 1.0000x reference)
#include <cuda_runtime.h>

// Problem constants
#define BB 128   // batch
#define UU 8     // in_unit
#define CC 2048  // in_channel (input capsules)
#define JJ 32    // num_unit (output capsules)
#define SS 16    // unit_size
#define NITER 3

// Derived
#define JS   (JJ*SS)        // 512
#define SU   (SS*UU)        // 128
#define JSU  (JJ*SS*UU)     // 4096
#define UC   (UU*CC)        // 16384
#define NCHUNK 16           // C split into 16 chunks of 128

// ---------------- device scratch (static; no allocation allowed) -------------
__device__ float g_xT[UU*CC*BB];            // [u][c][b]  (8 MB)
__device__ float g_b[CC*JJ];                // routing logits b[c][j]
__device__ float g_c[CC*JJ];                // softmax coeffs c[c][j]
__device__ float g_sp[NCHUNK*BB*JJ*SS];     // per-chunk partial s (4 MB)
__device__ float g_M[UC*JS];                // M[u*C+c][j*S+s] = sum_b xT*v (33.5 MB)

// ---------------- kernel 1: transpose x -> xT[u][c][b] -----------------------
__global__ void transpose_x_k(const float* __restrict__ x) {
    __shared__ float tile[32][33];
    int u  = blockIdx.z;
    int c0 = blockIdx.x * 32;
    int b0 = blockIdx.y * 32;
    int tx = threadIdx.x, ty = threadIdx.y;
    // read x[b0+ty][u][c0+tx]  (coalesced in c)
    tile[ty][tx] = x[(size_t)(b0 + ty) * (UU*CC) + (size_t)u * CC + c0 + tx];
    __syncthreads();
    // write xT[u][c0+ty][b0+tx] (coalesced in b)
    g_xT[(size_t)u * CC * BB + (size_t)(c0 + ty) * BB + b0 + tx] = tile[tx][ty];
}

// ---------------- kernel 2: zero b -------------------------------------------
__global__ void zero_b_k() {
    int i = blockIdx.x * blockDim.x + threadIdx.x;
    if (i < CC*JJ) g_b[i] = 0.0f;
}

// ---------------- kernel 3: softmax over C per j ------------------------------
__global__ void softmax_k() {
    int j = blockIdx.x;      // 32 blocks
    int t = threadIdx.x;     // 256 threads
    __shared__ float red[256];
    float vals[8];
    float mx = -1e30f;
    #pragma unroll
    for (int i = 0; i < 8; i++) {
        vals[i] = g_b[(i * 256 + t) * JJ + j];
        mx = fmaxf(mx, vals[i]);
    }
    red[t] = mx; __syncthreads();
    for (int o = 128; o > 0; o >>= 1) {
        if (t < o) red[t] = fmaxf(red[t], red[t + o]);
        __syncthreads();
    }
    mx = red[0]; __syncthreads();
    float sm = 0.0f;
    #pragma unroll
    for (int i = 0; i < 8; i++) { vals[i] = __expf(vals[i] - mx); sm += vals[i]; }
    red[t] = sm; __syncthreads();
    for (int o = 128; o > 0; o >>= 1) {
        if (t < o) red[t] += red[t + o];
        __syncthreads();
    }
    float inv = 1.0f / red[0];
    #pragma unroll
    for (int i = 0; i < 8; i++)
        g_c[(i * 256 + t) * JJ + j] = vals[i] * inv;
}

// ---------------- kernel 4: fused s-pass --------------------------------------
// s[b,j,s] = sum_c c[c,j] * sum_u W[c,j,s,u] * x[b,u,c]
// block = (j, c-chunk of 128), 128 threads (one per b). Writes per-chunk partials.
__global__ void __launch_bounds__(128) s_pass_k(const float* __restrict__ Wg) {
    int j     = blockIdx.x;   // 32
    int chunk = blockIdx.y;   // 16
    int b     = threadIdx.x;  // 128

    __shared__ float wsm[16 * 128];  // 16 c's of W[c][j][:][:]
    __shared__ float csm[16];

    float acc[SS];
    #pragma unroll
    for (int s = 0; s < SS; s++) acc[s] = 0.0f;

    int cbase = chunk * 128;
    for (int stage = 0; stage < 8; stage++) {
        int cs = cbase + stage * 16;
        #pragma unroll
        for (int k = 0; k < 16; k++)
            wsm[k * 128 + b] = Wg[(size_t)(cs + k) * JSU + (size_t)j * SU + b];
        if (b < 16) csm[b] = g_c[(cs + b) * JJ + j];
        __syncthreads();

        #pragma unroll 4
        for (int k = 0; k < 16; k++) {
            int c = cs + k;
            float coef = csm[k];
            float xv[UU];
            #pragma unroll
            for (int u = 0; u < UU; u++)
                xv[u] = coef * g_xT[(size_t)u * CC * BB + (size_t)c * BB + b];
            const float4* w4 = (const float4*)&wsm[k * 128];
            #pragma unroll
            for (int s = 0; s < SS; s++) {
                float4 wa = w4[s * 2];
                float4 wb = w4[s * 2 + 1];
                acc[s] += xv[0]*wa.x + xv[1]*wa.y + xv[2]*wa.z + xv[3]*wa.w
                        + xv[4]*wb.x + xv[5]*wb.y + xv[6]*wb.z + xv[7]*wb.w;
            }
        }
        __syncthreads();
    }
    #pragma unroll
    for (int s = 0; s < SS; s++)
        g_sp[(size_t)chunk * (BB*JS) + (size_t)b * JS + j * SS + s] = acc[s];
}

// ---------------- kernel 5: reduce partials + squash -> v (writes d_out) -----
__global__ void squash_k(float* __restrict__ out) {
    int b = blockIdx.x;      // 128
    int t = threadIdx.x;     // 512 = j*16 + s
    float sv = 0.0f;
    #pragma unroll
    for (int k = 0; k < NCHUNK; k++)
        sv += g_sp[(size_t)k * (BB*JS) + (size_t)b * JS + t];

    __shared__ float sq[512];
    __shared__ float msqs[SS];
    sq[t] = sv * sv;
    __syncthreads();
    if (t < SS) {
        float m = 0.0f;
        #pragma unroll
        for (int jj = 0; jj < JJ; jj++) m += sq[jj * SS + t];
        msqs[t] = m;
    }
    __syncthreads();
    float msq = msqs[t & (SS - 1)];
    float scale = msq / ((1.0f + msq) * sqrtf(msq));
    out[(size_t)b * JS + t] = sv * scale;
}

// ---------------- kernel 6: M = xT(16384x128) * v(128x512) --------------------
// 64x64 tile, K-tiles of 32, 128 threads, each thread 4x8 outputs.
__global__ void __launch_bounds__(128) mgemm_k(const float* __restrict__ v) {
    __shared__ float As[64][33];
    __shared__ float Bs[32][64];
    int col0 = blockIdx.x * 64;   // 8 col-blocks
    int row0 = blockIdx.y * 64;   // 256 row-blocks
    int t  = threadIdx.x;
    int tr = t >> 3;              // 0..15
    int tc = t & 7;               // 0..7

    float acc[4][8];
    #pragma unroll
    for (int i = 0; i < 4; i++)
        #pragma unroll
        for (int q = 0; q < 8; q++) acc[i][q] = 0.0f;

    for (int k0 = 0; k0 < BB; k0 += 32) {
        // load A tile: As[r][kk] = xT[(row0+r)*128 + k0+kk]
        #pragma unroll
        for (int i = 0; i < 16; i++) {
            int idx = i * 128 + t;
            int r  = idx >> 5;
            int kk = idx & 31;
            As[r][kk] = g_xT[(size_t)(row0 + r) * BB + k0 + kk];
        }
        // load B tile: Bs[kk][cc] = v[(k0+kk)*512 + col0+cc]
        #pragma unroll
        for (int i = 0; i < 16; i++) {
            int idx = i * 128 + t;
            int kk = idx >> 6;
            int cc = idx & 63;
            Bs[kk][cc] = v[(size_t)(k0 + kk) * JS + col0 + cc];
        }
        __syncthreads();
        #pragma unroll
        for (int kk = 0; kk < 32; kk++) {
            float a[4];
            #pragma unroll
            for (int i = 0; i < 4; i++) a[i] = As[tr * 4 + i][kk];
            const float4* brow = (const float4*)&Bs[kk][0];
            float4 b0 = brow[tc * 2];
            float4 b1 = brow[tc * 2 + 1];
            #pragma unroll
            for (int i = 0; i < 4; i++) {
                acc[i][0] += a[i] * b0.x;  acc[i][1] += a[i] * b0.y;
                acc[i][2] += a[i] * b0.z;  acc[i][3] += a[i] * b0.w;
                acc[i][4] += a[i] * b1.x;  acc[i][5] += a[i] * b1.y;
                acc[i][6] += a[i] * b1.z;  acc[i][7] += a[i] * b1.w;
            }
        }
        __syncthreads();
    }
    #pragma unroll
    for (int i = 0; i < 4; i++) {
        float4* dst = (float4*)&g_M[(size_t)(row0 + tr * 4 + i) * JS + col0 + tc * 8];
        dst[0] = make_float4(acc[i][0], acc[i][1], acc[i][2], acc[i][3]);
        dst[1] = make_float4(acc[i][4], acc[i][5], acc[i][6], acc[i][7]);
    }
}

// ---------------- kernel 7: b += (1/B) * sum_{s,u} W[c,j,s,u]*M[u,c,j,s] -----
__global__ void __launch_bounds__(128) bupdate_k(const float* __restrict__ Wg) {
    int j = blockIdx.x;                      // 32
    int c = blockIdx.y * 128 + threadIdx.x;  // 16 chunks x 128
    const float* wr = Wg + (size_t)c * JSU + (size_t)j * SU;  // [s][u], 128 floats
    float acc = 0.0f;
    #pragma unroll
    for (int u = 0; u < UU; u++) {
        const float4* m4 = (const float4*)&g_M[((size_t)u * CC + c) * JS + j * SS];
        #pragma unroll
        for (int sq = 0; sq < 4; sq++) {
            float4 m = m4[sq];
            acc += wr[(sq*4+0)*UU + u] * m.x
                 + wr[(sq*4+1)*UU + u] * m.y
                 + wr[(sq*4+2)*UU + u] * m.z
                 + wr[(sq*4+3)*UU + u] * m.w;
        }
    }
    g_b[c * JJ + j] += acc * (1.0f / (float)BB);
}

// ---------------- launcher ----------------------------------------------------
extern "C" void kernel_launch(void* const* d_in, const int* in_sizes, int n_in,
                              void* d_out, int out_size) {
    const float* x = (const float*)d_in[0];   // [B,U,C] = 2097152 floats
    const float* W = (const float*)d_in[1];   // [1,C,J,S,U] = 8388608 floats
    float* out = (float*)d_out;               // [B,J,S,1] = 65536 floats

    transpose_x_k<<<dim3(CC/32, BB/32, UU), dim3(32, 32)>>>(x);
    zero_b_k<<<(CC*JJ + 255) / 256, 256>>>();

    for (int it = 0; it < NITER; it++) {
        softmax_k<<<JJ, 256>>>();
        s_pass_k<<<dim3(JJ, NCHUNK), 128>>>(W);
        squash_k<<<BB, JS>>>(out);
        if (it < NITER - 1) {
            mgemm_k<<<dim3(JS/64, UC/64), 128>>>(out);
            bupdate_k<<<dim3(JJ, NCHUNK), 128>>>(W);
        }
    }
}

// round 2
// speedup vs baseline: 1.1550x; 1.1550x over previous
#include <cuda_runtime.h>

// Problem constants
#define BB 128   // batch
#define UU 8     // in_unit
#define CC 2048  // in_channel
#define JJ 32    // num_unit
#define SS 16    // unit_size
#define NITER 3

#define JS   (JJ*SS)        // 512
#define SU   (SS*UU)        // 128
#define JSU  (JJ*SS*UU)     // 4096
#define UC   (UU*CC)        // 16384
#define NCHUNK 64           // C split into 64 chunks of 32

typedef unsigned long long ull;

// ---------------- packed f32x2 helpers ---------------------------------------
__device__ __forceinline__ ull pk2(float lo, float hi) {
    ull r; asm("mov.b64 %0, {%1, %2};" : "=l"(r) : "f"(lo), "f"(hi)); return r;
}
__device__ __forceinline__ void fma2(ull& d, ull a, ull b) {
    asm("fma.rn.f32x2 %0, %1, %2, %0;" : "+l"(d) : "l"(a), "l"(b));
}
__device__ __forceinline__ void upk2(float& lo, float& hi, ull v) {
    asm("mov.b64 {%0, %1}, %2;" : "=f"(lo), "=f"(hi) : "l"(v));
}

// ---------------- device scratch ----------------------------------------------
__device__ float g_xT[UU*CC*BB];            // [u][c][b]  (8 MB)
__device__ float g_Wr[CC*JSU];              // W reordered [c][j][u][s] (33.5 MB)
__device__ float g_b[CC*JJ];
__device__ float g_c[CC*JJ];
__device__ float g_sp[NCHUNK*BB*JS];        // per-chunk partial s (16 MB)
__device__ float g_M[UC*JS];                // M[u*C+c][j*S+s] (33.5 MB)

// ---------------- kernel 1: transpose x -> xT[u][c][b] ------------------------
__global__ void transpose_x_k(const float* __restrict__ x) {
    __shared__ float tile[32][33];
    int u  = blockIdx.z;
    int c0 = blockIdx.x * 32;
    int b0 = blockIdx.y * 32;
    int tx = threadIdx.x, ty = threadIdx.y;
    tile[ty][tx] = x[(size_t)(b0 + ty) * (UU*CC) + (size_t)u * CC + c0 + tx];
    __syncthreads();
    g_xT[(size_t)u * CC * BB + (size_t)(c0 + ty) * BB + b0 + tx] = tile[tx][ty];
}

// ---------------- kernel 1b: reorder W[c][j][s][u] -> Wr[c][j][u][s] ----------
__global__ void reorder_w_k(const float* __restrict__ Wg) {
    // one block per 2 (c,j) rows; 256 threads
    int row = blockIdx.x * 2 + (threadIdx.x >> 7);  // (c*J + j)
    int t   = threadIdx.x & 127;                    // output idx u*16+s
    int u = t >> 4, s = t & 15;
    g_Wr[(size_t)row * SU + t] = Wg[(size_t)row * SU + s * UU + u];
}

// ---------------- kernel 2: zero b --------------------------------------------
__global__ void zero_b_k() {
    int i = blockIdx.x * blockDim.x + threadIdx.x;
    if (i < CC*JJ) g_b[i] = 0.0f;
}

// ---------------- kernel 3: softmax over C per j ------------------------------
__global__ void softmax_k() {
    int j = blockIdx.x;
    int t = threadIdx.x;     // 256
    __shared__ float red[256];
    float vals[8];
    float mx = -1e30f;
    #pragma unroll
    for (int i = 0; i < 8; i++) {
        vals[i] = g_b[(i * 256 + t) * JJ + j];
        mx = fmaxf(mx, vals[i]);
    }
    red[t] = mx; __syncthreads();
    for (int o = 128; o > 0; o >>= 1) {
        if (t < o) red[t] = fmaxf(red[t], red[t + o]);
        __syncthreads();
    }
    mx = red[0]; __syncthreads();
    float sm = 0.0f;
    #pragma unroll
    for (int i = 0; i < 8; i++) { vals[i] = __expf(vals[i] - mx); sm += vals[i]; }
    red[t] = sm; __syncthreads();
    for (int o = 128; o > 0; o >>= 1) {
        if (t < o) red[t] += red[t + o];
        __syncthreads();
    }
    float inv = 1.0f / red[0];
    #pragma unroll
    for (int i = 0; i < 8; i++)
        g_c[(i * 256 + t) * JJ + j] = vals[i] * inv;
}

// ---------------- kernel 4: fused s-pass (f32x2) ------------------------------
// s[b,j,s] = sum_c c[c,j] * sum_u Wr[c,j,u,s] * x[b,u,c]
// block = (j, c-chunk of 32), 128 threads (one per b).
__global__ void __launch_bounds__(128) s_pass_k(int dummy) {
    int j     = blockIdx.x;   // 32
    int chunk = blockIdx.y;   // 64
    int b     = threadIdx.x;  // 128

    __shared__ __align__(16) float wsm[32 * 128];  // 32 c's of Wr[c][j][u][s]
    __shared__ float csm[32];

    int cbase = chunk * 32;
    // cooperative load: 32 rows x 32 float4
    {
        const float4* Wr4 = (const float4*)g_Wr;
        float4* w4 = (float4*)wsm;
        #pragma unroll
        for (int i = 0; i < 8; i++) {
            int lin = i * 128 + b;        // 0..1023
            int k = lin >> 5;             // c within chunk
            int q = lin & 31;             // float4 within row
            w4[lin] = Wr4[(size_t)(cbase + k) * (JSU/4) + j * 32 + q];
        }
        if (b < 32) csm[b] = g_c[(cbase + b) * JJ + j];
    }
    __syncthreads();

    ull acc2[8];
    #pragma unroll
    for (int sp = 0; sp < 8; sp++) acc2[sp] = pk2(0.0f, 0.0f);

    const float* xbase = g_xT + b;
    #pragma unroll 2
    for (int k = 0; k < 32; k++) {
        int c = cbase + k;
        float coef = csm[k];
        ull xd[UU];
        #pragma unroll
        for (int u = 0; u < UU; u++) {
            float xv = coef * xbase[(size_t)u * (CC*BB) + (size_t)c * BB];
            xd[u] = pk2(xv, xv);
        }
        const ull* w2 = (const ull*)&wsm[k * 128];  // [u*8 + sp]
        #pragma unroll
        for (int u = 0; u < UU; u++) {
            #pragma unroll
            for (int sp = 0; sp < 8; sp++)
                fma2(acc2[sp], w2[u * 8 + sp], xd[u]);
        }
    }

    float res[SS];
    #pragma unroll
    for (int sp = 0; sp < 8; sp++) upk2(res[2*sp], res[2*sp+1], acc2[sp]);
    float4* dst = (float4*)&g_sp[(size_t)chunk * (BB*JS) + (size_t)b * JS + j * SS];
    #pragma unroll
    for (int q = 0; q < 4; q++)
        dst[q] = make_float4(res[q*4], res[q*4+1], res[q*4+2], res[q*4+3]);
}

// ---------------- kernel 5: reduce partials + squash -> v ---------------------
__global__ void squash_k(float* __restrict__ out) {
    int b = blockIdx.x;      // 128
    int t = threadIdx.x;     // 512 = j*16 + s
    float sv = 0.0f;
    #pragma unroll 8
    for (int k = 0; k < NCHUNK; k++)
        sv += g_sp[(size_t)k * (BB*JS) + (size_t)b * JS + t];

    __shared__ float sq[512];
    __shared__ float msqs[SS];
    sq[t] = sv * sv;
    __syncthreads();
    if (t < SS) {
        float m = 0.0f;
        #pragma unroll
        for (int jj = 0; jj < JJ; jj++) m += sq[jj * SS + t];
        msqs[t] = m;
    }
    __syncthreads();
    float msq = msqs[t & (SS - 1)];
    float scale = msq / ((1.0f + msq) * sqrtf(msq));
    out[(size_t)b * JS + t] = sv * scale;
}

// ---------------- kernel 6: M = xT(16384x128) * v(128x512), f32x2 -------------
__global__ void __launch_bounds__(128) mgemm_k(const float* __restrict__ v) {
    __shared__ float As[64][33];
    __shared__ __align__(16) float Bs[32][64];
    int col0 = blockIdx.x * 64;   // 8
    int row0 = blockIdx.y * 64;   // 256
    int t  = threadIdx.x;
    int tr = t >> 3;              // 0..15
    int tc = t & 7;               // 0..7

    ull acc2[4][4];
    #pragma unroll
    for (int i = 0; i < 4; i++)
        #pragma unroll
        for (int q = 0; q < 4; q++) acc2[i][q] = pk2(0.0f, 0.0f);

    for (int k0 = 0; k0 < BB; k0 += 32) {
        #pragma unroll
        for (int i = 0; i < 16; i++) {
            int idx = i * 128 + t;
            int r  = idx >> 5;
            int kk = idx & 31;
            As[r][kk] = g_xT[(size_t)(row0 + r) * BB + k0 + kk];
        }
        #pragma unroll
        for (int i = 0; i < 16; i++) {
            int idx = i * 128 + t;
            int kk = idx >> 6;
            int cc = idx & 63;
            Bs[kk][cc] = v[(size_t)(k0 + kk) * JS + col0 + cc];
        }
        __syncthreads();
        #pragma unroll
        for (int kk = 0; kk < 32; kk++) {
            const ull* brow = (const ull*)&Bs[kk][0];
            ull b2[4];
            #pragma unroll
            for (int q = 0; q < 4; q++) b2[q] = brow[tc * 4 + q];
            #pragma unroll
            for (int i = 0; i < 4; i++) {
                float a = As[tr * 4 + i][kk];
                ull ad = pk2(a, a);
                #pragma unroll
                for (int q = 0; q < 4; q++) fma2(acc2[i][q], b2[q], ad);
            }
        }
        __syncthreads();
    }
    #pragma unroll
    for (int i = 0; i < 4; i++) {
        float r[8];
        #pragma unroll
        for (int q = 0; q < 4; q++) upk2(r[2*q], r[2*q+1], acc2[i][q]);
        float4* dst = (float4*)&g_M[(size_t)(row0 + tr * 4 + i) * JS + col0 + tc * 8];
        dst[0] = make_float4(r[0], r[1], r[2], r[3]);
        dst[1] = make_float4(r[4], r[5], r[6], r[7]);
    }
}

// ---------------- kernel 7: b += (1/B) * sum_{s,u} Wr[c,j,u,s]*M[u,c,j,s] -----
__global__ void __launch_bounds__(128) bupdate_k(int dummy) {
    int j = blockIdx.x;                      // 32
    int c = blockIdx.y * 128 + threadIdx.x;  // 16 x 128
    const float4* wr4 = (const float4*)(g_Wr + (size_t)c * JSU + (size_t)j * SU);
    float acc = 0.0f;
    #pragma unroll
    for (int u = 0; u < UU; u++) {
        const float4* m4 = (const float4*)&g_M[((size_t)u * CC + c) * JS + j * SS];
        #pragma unroll
        for (int q = 0; q < 4; q++) {
            float4 w = wr4[u * 4 + q];
            float4 m = m4[q];
            acc += w.x*m.x + w.y*m.y + w.z*m.z + w.w*m.w;
        }
    }
    g_b[c * JJ + j] += acc * (1.0f / (float)BB);
}

// ---------------- launcher ----------------------------------------------------
extern "C" void kernel_launch(void* const* d_in, const int* in_sizes, int n_in,
                              void* d_out, int out_size) {
    const float* x = (const float*)d_in[0];   // [B,U,C]
    const float* W = (const float*)d_in[1];   // [1,C,J,S,U]
    float* out = (float*)d_out;               // [B,J,S,1]

    transpose_x_k<<<dim3(CC/32, BB/32, UU), dim3(32, 32)>>>(x);
    reorder_w_k<<<CC*JJ/2, 256>>>(W);
    zero_b_k<<<(CC*JJ + 255) / 256, 256>>>();

    for (int it = 0; it < NITER; it++) {
        softmax_k<<<JJ, 256>>>();
        s_pass_k<<<dim3(JJ, NCHUNK), 128>>>(0);
        squash_k<<<BB, JS>>>(out);
        if (it < NITER - 1) {
            mgemm_k<<<dim3(JS/64, UC/64), 128>>>(out);
            bupdate_k<<<dim3(JJ, NCHUNK/4), 128>>>(0);
        }
    }
}

// round 3
// speedup vs baseline: 1.3723x; 1.1881x over previous
#include <cuda_runtime.h>

#define BB 128
#define UU 8
#define CC 2048
#define JJ 32
#define SS 16
#define NITER 3

#define JS   (JJ*SS)     // 512
#define SU   (SS*UU)     // 128
#define JSU  (JJ*SS*UU)  // 4096
#define UC   (UU*CC)     // 16384
#define CB   (CC*BB)
#define NCHUNK 32        // 32 chunks of 64 c

typedef unsigned long long ull;

// ---------------- packed f32x2 helpers ---------------------------------------
__device__ __forceinline__ ull pk2(float lo, float hi) {
    ull r; asm("mov.b64 %0, {%1, %2};" : "=l"(r) : "f"(lo), "f"(hi)); return r;
}
__device__ __forceinline__ void fma2(ull& d, ull a, ull b) {
    asm("fma.rn.f32x2 %0, %1, %2, %0;" : "+l"(d) : "l"(a), "l"(b));
}
__device__ __forceinline__ void add2(ull& d, ull a) {
    asm("add.rn.f32x2 %0, %0, %1;" : "+l"(d) : "l"(a));
}
__device__ __forceinline__ void upk2(float& lo, float& hi, ull v) {
    asm("mov.b64 {%0, %1}, %2;" : "=f"(lo), "=f"(hi) : "l"(v));
}

// ---------------- device scratch ----------------------------------------------
__device__ float g_xT[UU*CC*BB];       // [u][c][b]  8 MB
__device__ float g_Wr[CC*JSU];         // [c][j][u][s] 33.5 MB
__device__ float g_b[JJ*CC];           // logits [j][c]
__device__ float g_c[JJ*CC];           // coeffs [j][c]
__device__ float g_sp[NCHUNK*BB*JS];   // partial s, 8 MB
__device__ float g_M[UC*JS];           // M[(u,c)][(j,s)] 33.5 MB

// ---------------- transpose x -> xT[u][c][b] -----------------------------------
__global__ void transpose_x_k(const float* __restrict__ x) {
    __shared__ float tile[32][33];
    int u  = blockIdx.z;
    int c0 = blockIdx.x * 32;
    int b0 = blockIdx.y * 32;
    int tx = threadIdx.x, ty = threadIdx.y;
    tile[ty][tx] = x[(size_t)(b0 + ty) * (UU*CC) + (size_t)u * CC + c0 + tx];
    __syncthreads();
    g_xT[(size_t)u * CB + (size_t)(c0 + ty) * BB + b0 + tx] = tile[tx][ty];
}

// ---------------- reorder W[c][j][s][u] -> Wr[c][j][u][s] -----------------------
__global__ void reorder_w_k(const float* __restrict__ Wg) {
    int row = blockIdx.x * 2 + (threadIdx.x >> 7);  // c*J + j
    int t   = threadIdx.x & 127;                    // u*16+s
    int u = t >> 4, s = t & 15;
    g_Wr[(size_t)row * SU + t] = Wg[(size_t)row * SU + s * UU + u];
}

// ---------------- init: b=0, c=1/2048 (softmax of zeros) ------------------------
__global__ void init_k() {
    int i = blockIdx.x * blockDim.x + threadIdx.x;
    if (i < JJ*CC) { g_b[i] = 0.0f; g_c[i] = 1.0f / 2048.0f; }
}

// ---------------- softmax over c for each j (coalesced) -------------------------
__global__ void softmax_k() {
    int j = blockIdx.x;       // 32
    int t = threadIdx.x;      // 512
    __shared__ float redm[16];
    __shared__ float reds[16];
    const float4* bp = (const float4*)(g_b + (size_t)j * CC);
    float4 v = bp[t];
    float mx = fmaxf(fmaxf(v.x, v.y), fmaxf(v.z, v.w));
    #pragma unroll
    for (int o = 16; o > 0; o >>= 1) mx = fmaxf(mx, __shfl_xor_sync(0xffffffffu, mx, o));
    if ((t & 31) == 0) redm[t >> 5] = mx;
    __syncthreads();
    float bmax = redm[0];
    #pragma unroll
    for (int i = 1; i < 16; i++) bmax = fmaxf(bmax, redm[i]);
    float4 e;
    e.x = __expf(v.x - bmax); e.y = __expf(v.y - bmax);
    e.z = __expf(v.z - bmax); e.w = __expf(v.w - bmax);
    float sm = e.x + e.y + e.z + e.w;
    #pragma unroll
    for (int o = 16; o > 0; o >>= 1) sm += __shfl_xor_sync(0xffffffffu, sm, o);
    if ((t & 31) == 0) reds[t >> 5] = sm;
    __syncthreads();
    float tot = 0.0f;
    #pragma unroll
    for (int i = 0; i < 16; i++) tot += reds[i];
    float inv = 1.0f / tot;
    e.x *= inv; e.y *= inv; e.z *= inv; e.w *= inv;
    ((float4*)(g_c + (size_t)j * CC))[t] = e;
}

// ---------------- fused s-pass ---------------------------------------------------
// s[b,j,s] = sum_c coef[j,c] * sum_u Wr[c,j,u,s] * xT[u,c,b]
// block = (j, chunk of 64 c), 128 thr; lane owns b = lane + {0,32,64,96};
// warp w covers 16 c. W broadcast-read from smem; coef folded at stage time.
__global__ void __launch_bounds__(128) s_pass_k() {
    int j     = blockIdx.x;   // 32
    int chunk = blockIdx.y;   // 32
    int t     = threadIdx.x;
    int w = t >> 5, lane = t & 31;
    int cbase = chunk * 64;

    __shared__ __align__(16) float wsm[64 * 128];  // 32 KB

    // stage coef-scaled W
    {
        const float4* Wr4 = (const float4*)g_Wr;
        float4* w4 = (float4*)wsm;
        #pragma unroll
        for (int i = 0; i < 16; i++) {
            int lin = i * 128 + t;          // 0..2047
            int cl = lin >> 5, q = lin & 31;
            float coef = __ldg(&g_c[(size_t)j * CC + cbase + cl]);
            float4 wv = Wr4[(size_t)(cbase + cl) * (JSU/4) + j * 32 + q];
            wv.x *= coef; wv.y *= coef; wv.z *= coef; wv.w *= coef;
            w4[cl * 32 + q] = wv;
        }
    }
    __syncthreads();

    ull acc[4][8];
    #pragma unroll
    for (int bi = 0; bi < 4; bi++)
        #pragma unroll
        for (int sp = 0; sp < 8; sp++) acc[bi][sp] = 0ULL;

    const float* xb = g_xT + lane;
    int c0 = cbase + w * 16;

    #pragma unroll 1
    for (int k = 0; k < 16; k++) {
        int c  = c0 + k;
        int cl = c - cbase;
        #pragma unroll
        for (int u = 0; u < UU; u++) {
            const float* xp = xb + (size_t)u * CB + (size_t)c * BB;
            float x0 = __ldg(xp);
            float x1 = __ldg(xp + 32);
            float x2 = __ldg(xp + 64);
            float x3 = __ldg(xp + 96);
            ull xd0 = pk2(x0, x0), xd1 = pk2(x1, x1);
            ull xd2 = pk2(x2, x2), xd3 = pk2(x3, x3);
            const ulonglong2* w2 = (const ulonglong2*)&wsm[cl * 128 + u * 16];
            ulonglong2 wv0 = w2[0], wv1 = w2[1], wv2 = w2[2], wv3 = w2[3];
            fma2(acc[0][0], wv0.x, xd0); fma2(acc[1][0], wv0.x, xd1);
            fma2(acc[2][0], wv0.x, xd2); fma2(acc[3][0], wv0.x, xd3);
            fma2(acc[0][1], wv0.y, xd0); fma2(acc[1][1], wv0.y, xd1);
            fma2(acc[2][1], wv0.y, xd2); fma2(acc[3][1], wv0.y, xd3);
            fma2(acc[0][2], wv1.x, xd0); fma2(acc[1][2], wv1.x, xd1);
            fma2(acc[2][2], wv1.x, xd2); fma2(acc[3][2], wv1.x, xd3);
            fma2(acc[0][3], wv1.y, xd0); fma2(acc[1][3], wv1.y, xd1);
            fma2(acc[2][3], wv1.y, xd2); fma2(acc[3][3], wv1.y, xd3);
            fma2(acc[0][4], wv2.x, xd0); fma2(acc[1][4], wv2.x, xd1);
            fma2(acc[2][4], wv2.x, xd2); fma2(acc[3][4], wv2.x, xd3);
            fma2(acc[0][5], wv2.y, xd0); fma2(acc[1][5], wv2.y, xd1);
            fma2(acc[2][5], wv2.y, xd2); fma2(acc[3][5], wv2.y, xd3);
            fma2(acc[0][6], wv3.x, xd0); fma2(acc[1][6], wv3.x, xd1);
            fma2(acc[2][6], wv3.x, xd2); fma2(acc[3][6], wv3.x, xd3);
            fma2(acc[0][7], wv3.y, xd0); fma2(acc[1][7], wv3.y, xd1);
            fma2(acc[2][7], wv3.y, xd2); fma2(acc[3][7], wv3.y, xd3);
        }
    }

    // block reduce across the 4 warps (each has full b, partial c)
    __syncthreads();
    ull* redU = (ull*)wsm;   // 4096 ULL = 32 KB
    #pragma unroll
    for (int bi = 0; bi < 4; bi++)
        #pragma unroll
        for (int sp = 0; sp < 8; sp++)
            redU[w * 1024 + sp * 128 + bi * 32 + lane] = acc[bi][sp];
    __syncthreads();

    // thread t owns b = t
    float res[16];
    #pragma unroll
    for (int sp = 0; sp < 8; sp++) {
        ull s = redU[sp * 128 + t];
        add2(s, redU[1024 + sp * 128 + t]);
        add2(s, redU[2048 + sp * 128 + t]);
        add2(s, redU[3072 + sp * 128 + t]);
        upk2(res[2*sp], res[2*sp+1], s);
    }
    float4* dst = (float4*)&g_sp[(size_t)chunk * (BB*JS) + (size_t)t * JS + j * SS];
    #pragma unroll
    for (int q = 0; q < 4; q++)
        dst[q] = make_float4(res[q*4], res[q*4+1], res[q*4+2], res[q*4+3]);
}

// ---------------- reduce partials + squash -> v ---------------------------------
__global__ void squash_k(float* __restrict__ out) {
    int b = blockIdx.x;      // 128
    int t = threadIdx.x;     // 512
    float sv = 0.0f;
    #pragma unroll 8
    for (int k = 0; k < NCHUNK; k++)
        sv += g_sp[(size_t)k * (BB*JS) + (size_t)b * JS + t];

    __shared__ float sq[512];
    __shared__ float msqs[SS];
    sq[t] = sv * sv;
    __syncthreads();
    if (t < SS) {
        float m = 0.0f;
        #pragma unroll
        for (int jj = 0; jj < JJ; jj++) m += sq[jj * SS + t];
        msqs[t] = m;
    }
    __syncthreads();
    float msq = msqs[t & (SS - 1)];
    float scale = msq / ((1.0f + msq) * sqrtf(msq));
    out[(size_t)b * JS + t] = sv * scale;
}

// ---------------- M = xT(16384x128) * v(128x512) --------------------------------
// 128x128 tile, 128 threads, 8x16 per thread, f32x2.
#define PADA 132
__global__ void __launch_bounds__(128) mgemm_k(const float* __restrict__ v) {
    __shared__ __align__(16) float As[32 * PADA];  // [kk][r], padded
    __shared__ __align__(16) float Bs[32 * 128];   // [kk][cc]
    int col0 = blockIdx.x * 128;   // 4
    int row0 = blockIdx.y * 128;   // 128
    int t  = threadIdx.x;
    int tr = t >> 3;               // 0..15 -> rows tr*8..+8
    int tc = t & 7;                // 0..7  -> cols tc*16..+16

    ull acc[8][8];
    #pragma unroll
    for (int i = 0; i < 8; i++)
        #pragma unroll
        for (int q = 0; q < 8; q++) acc[i][q] = 0ULL;

    for (int k0 = 0; k0 < BB; k0 += 32) {
        // stage A (transposed to [kk][r])
        #pragma unroll
        for (int i = 0; i < 8; i++) {
            int lin = i * 128 + t;          // float4 units, 0..1023
            int r = lin >> 3, kq = lin & 7;
            float4 a = *(const float4*)&g_xT[(size_t)(row0 + r) * BB + k0 + kq * 4];
            As[(kq*4+0) * PADA + r] = a.x;
            As[(kq*4+1) * PADA + r] = a.y;
            As[(kq*4+2) * PADA + r] = a.z;
            As[(kq*4+3) * PADA + r] = a.w;
        }
        // stage B
        #pragma unroll
        for (int i = 0; i < 8; i++) {
            int lin = i * 128 + t;
            int kk = lin >> 5, cq = lin & 31;
            ((float4*)Bs)[kk * 32 + cq] =
                *(const float4*)&v[(size_t)(k0 + kk) * JS + col0 + cq * 4];
        }
        __syncthreads();
        #pragma unroll
        for (int kk = 0; kk < 32; kk++) {
            const float4* ap = (const float4*)&As[kk * PADA + tr * 8];
            float4 a0 = ap[0], a1 = ap[1];
            const ulonglong2* bp = (const ulonglong2*)&Bs[kk * 128 + tc * 16];
            ulonglong2 b0 = bp[0], b1 = bp[1], b2 = bp[2], b3 = bp[3];
            float ar[8] = {a0.x, a0.y, a0.z, a0.w, a1.x, a1.y, a1.z, a1.w};
            #pragma unroll
            for (int ri = 0; ri < 8; ri++) {
                ull ad = pk2(ar[ri], ar[ri]);
                fma2(acc[ri][0], b0.x, ad);
                fma2(acc[ri][1], b0.y, ad);
                fma2(acc[ri][2], b1.x, ad);
                fma2(acc[ri][3], b1.y, ad);
                fma2(acc[ri][4], b2.x, ad);
                fma2(acc[ri][5], b2.y, ad);
                fma2(acc[ri][6], b3.x, ad);
                fma2(acc[ri][7], b3.y, ad);
            }
        }
        __syncthreads();
    }
    #pragma unroll
    for (int ri = 0; ri < 8; ri++) {
        float r[16];
        #pragma unroll
        for (int q = 0; q < 8; q++) upk2(r[2*q], r[2*q+1], acc[ri][q]);
        float4* dst = (float4*)&g_M[(size_t)(row0 + tr*8 + ri) * JS + col0 + tc * 16];
        dst[0] = make_float4(r[0],  r[1],  r[2],  r[3]);
        dst[1] = make_float4(r[4],  r[5],  r[6],  r[7]);
        dst[2] = make_float4(r[8],  r[9],  r[10], r[11]);
        dst[3] = make_float4(r[12], r[13], r[14], r[15]);
    }
}

// ---------------- b[j,c] += (1/B) sum_{u,s} Wr[c,j,u,s]*M[(u,c),(j,s)] ----------
__global__ void __launch_bounds__(128) bupdate_k() {
    int j = blockIdx.x;                      // 32
    int c = blockIdx.y * 128 + threadIdx.x;  // 16 x 128
    const float4* wr4 = (const float4*)(g_Wr + (size_t)c * JSU + (size_t)j * SU);
    float acc = 0.0f;
    #pragma unroll
    for (int u = 0; u < UU; u++) {
        const float4* m4 = (const float4*)&g_M[((size_t)u * CC + c) * JS + j * SS];
        #pragma unroll
        for (int q = 0; q < 4; q++) {
            float4 wv = wr4[u * 4 + q];
            float4 m  = m4[q];
            acc += wv.x*m.x + wv.y*m.y + wv.z*m.z + wv.w*m.w;
        }
    }
    g_b[(size_t)j * CC + c] += acc * (1.0f / (float)BB);
}

// ---------------- launcher --------------------------------------------------------
extern "C" void kernel_launch(void* const* d_in, const int* in_sizes, int n_in,
                              void* d_out, int out_size) {
    const float* x = (const float*)d_in[0];   // [B,U,C]
    const float* W = (const float*)d_in[1];   // [1,C,J,S,U]
    float* out = (float*)d_out;               // [B,J,S,1]

    transpose_x_k<<<dim3(CC/32, BB/32, UU), dim3(32, 32)>>>(x);
    reorder_w_k<<<CC*JJ/2, 256>>>(W);
    init_k<<<(JJ*CC + 255)/256, 256>>>();

    for (int it = 0; it < NITER; it++) {
        if (it > 0) softmax_k<<<JJ, 512>>>();   // iter 0: uniform coeffs from init
        s_pass_k<<<dim3(JJ, NCHUNK), 128>>>();
        squash_k<<<BB, 512>>>(out);
        if (it < NITER - 1) {
            mgemm_k<<<dim3(JS/128, UC/128), 128>>>(out);
            bupdate_k<<<dim3(JJ, CC/128), 128>>>();
        }
    }
}